// round 1
// baseline (speedup 1.0000x reference)
#include <cuda_runtime.h>

// Histogram2d: x[32,16384,64] f32 in [0,1) -> hist[32,128,64] * weights[128,64]
//
// Strategy: per-thread private u16 histograms in SMEM (zero atomics),
// packed-u16 intra-block reduction, coalesced partial dump to global scratch,
// tiny second kernel for final sum + weight multiply.

constexpr int B = 32, S = 16384, F = 64, BINS = 128;
constexpr int C = 16;                  // chunks per batch
constexpr int CHUNK = S / C;           // 1024 rows per block
constexpr int THREADS = 256;
constexpr int HWORDS = 65;             // 64 data words (128 u16 bins) + 1 pad -> stride 65 (conflict-free)
constexpr int SMEM_BYTES = THREADS * HWORDS * 4;   // 66560 B -> 3 blocks/SM

// Per-(chunk,batch) partial histograms: [C][B][BINS*F] u32 = 16 MB
__device__ __align__(16) unsigned int g_scratch[(size_t)C * B * BINS * F];

__global__ __launch_bounds__(THREADS, 3)
void hist_kernel(const float* __restrict__ x) {
    extern __shared__ unsigned int sh[];
    const int tid = threadIdx.x;
    const int w = tid >> 5, l = tid & 31;

    // zero own (padded) histogram; private -> no sync needed before main loop
    unsigned int* my = sh + tid * HWORDS;
#pragma unroll
    for (int i = 0; i < HWORDS; i++) my[i] = 0u;
    unsigned short* h16 = reinterpret_cast<unsigned short*>(my);

    const int fh = w & 1;        // feature half: 0 -> f 0..31, 1 -> f 32..63
    const int soff = w >> 1;     // row offset mod 4
    const int f = fh * 32 + l;
    const int b = blockIdx.y, c = blockIdx.x;

    const float* base = x + (((size_t)b * S + (size_t)c * CHUNK + soff) * F + f);

    constexpr int ITERS = CHUNK / 4;   // 256 rows per thread
    constexpr int U = 8;               // load-ahead for MLP
#pragma unroll 1
    for (int i = 0; i < ITERS; i += U) {
        float v[U];
#pragma unroll
        for (int u = 0; u < U; u++)
            v[u] = __ldcs(base + (size_t)(i + u) * (4 * F));
#pragma unroll
        for (int u = 0; u < U; u++) {
            int bin = (int)(v[u] * 128.0f);            // trunc, matches .int()
            bin = bin < 0 ? 0 : (bin > BINS - 1 ? BINS - 1 : bin);
            h16[bin] = (unsigned short)(h16[bin] + 1); // private: no atomics
        }
    }
    __syncthreads();

    // Intra-block reduction over the 4 s-offsets + coalesced dump of partials.
    // unit u -> (m = bin pair index, fo = feature). Packed u16x2 adds are safe:
    // per-thread per-bin count <= 256, sum of 4 <= 1024 -> no carry into hi half.
    unsigned int* outp = g_scratch + ((size_t)c * B + b) * (BINS * F);
#pragma unroll
    for (int k = 0; k < 16; k++) {
        const int u = tid + THREADS * k;
        const int fo = u & 63;
        const int m  = u >> 6;                 // 0..63 (bins 2m, 2m+1)
        const int fh2 = fo >> 5, fl = fo & 31;
        unsigned int sum = 0;
#pragma unroll
        for (int s = 0; s < 4; s++) {
            const int tsrc = (s * 2 + fh2) * 32 + fl;
            sum += sh[(size_t)tsrc * HWORDS + m];   // conflict-free (stride 65)
        }
        outp[(2 * m) * F + fo]     = sum & 0xFFFFu;  // coalesced STG.32
        outp[(2 * m + 1) * F + fo] = sum >> 16;
    }
}

__global__ void reduce_kernel(const float* __restrict__ wts, float* __restrict__ out) {
    const int idx = blockIdx.x * blockDim.x + threadIdx.x;  // 0..65535
    const int b = idx >> 11;                // / 2048
    const int p4 = (idx & 2047) << 2;       // 16B-aligned position in [0, 8192)
    unsigned int a0 = 0, a1 = 0, a2 = 0, a3 = 0;
#pragma unroll
    for (int c = 0; c < C; c++) {
        const uint4 v = *reinterpret_cast<const uint4*>(
            g_scratch + ((size_t)(c * B + b)) * (BINS * F) + p4);
        a0 += v.x; a1 += v.y; a2 += v.z; a3 += v.w;
    }
    const float4 wv = *reinterpret_cast<const float4*>(wts + p4);
    float4 o;
    o.x = (float)a0 * wv.x;
    o.y = (float)a1 * wv.y;
    o.z = (float)a2 * wv.z;
    o.w = (float)a3 * wv.w;
    *reinterpret_cast<float4*>(out + (size_t)b * (BINS * F) + p4) = o;
}

extern "C" void kernel_launch(void* const* d_in, const int* in_sizes, int n_in,
                              void* d_out, int out_size) {
    const float* x   = (const float*)d_in[0];
    const float* wts = (const float*)d_in[1];
    float* out = (float*)d_out;

    cudaFuncSetAttribute(hist_kernel, cudaFuncAttributeMaxDynamicSharedMemorySize, SMEM_BYTES);

    dim3 grid(C, B);   // 16 x 32 = 512 blocks
    hist_kernel<<<grid, THREADS, SMEM_BYTES>>>(x);
    reduce_kernel<<<(B * BINS * F / 4) / THREADS, THREADS>>>(wts, out);
}

// round 2
// speedup vs baseline: 1.3941x; 1.3941x over previous
#include <cuda_runtime.h>

// Histogram2d: x[32,16384,64] f32 in [0,1) -> hist[32,128,64] * weights[128,64]
//
// Per-thread private u8 histograms in SMEM (zero atomics), occ 6 (48 warps/SM),
// single balanced wave (544 blocks), dp4a-based intra-block reduction,
// coalesced u32 partial dump to global scratch, tiny final reduce kernel.

constexpr int B = 32, S = 16384, F = 64, BINS = 128;
constexpr int NCHUNK = 17;             // chunks per batch -> <=241 rows/thread (u8-safe)
constexpr int CHUNK = 964;             // 16*964 + 960 = 16384
constexpr int THREADS = 256;
constexpr int HWORDS = 33;             // 32 data words (128 u8 bins) + 1 pad (stride 33: conflict-free dump)
constexpr int SMEM_BYTES = THREADS * HWORDS * 4;   // 33792 B -> 6 blocks/SM

// Per-(chunk,batch) partial histograms: [NCHUNK][B][BINS*F] u32 = 17.8 MB
__device__ __align__(16) unsigned int g_scratch[(size_t)NCHUNK * B * BINS * F];

// no-op kernels to phase-align ncu -s 5 -c 1 onto hist_kernel (launch #6 = pos 2 of call 2)
__global__ void dummy_kernel() {}

__global__ __launch_bounds__(THREADS, 6)
void hist_kernel(const float* __restrict__ x) {
    extern __shared__ unsigned int sh[];
    const int tid = threadIdx.x;
    const int w = tid >> 5, l = tid & 31;

    // zero own (padded) histogram; private -> no sync needed before main loop
    unsigned int* my = sh + tid * HWORDS;
#pragma unroll
    for (int i = 0; i < HWORDS; i++) my[i] = 0u;
    unsigned char* h8 = reinterpret_cast<unsigned char*>(my);

    const int fh = w & 1;        // feature half: 0 -> f 0..31, 1 -> f 32..63
    const int soff = w >> 1;     // row offset mod 4
    const int f = fh * 32 + l;
    const int b = blockIdx.y, c = blockIdx.x;

    const int row0 = c * CHUNK;
    const int rows = min(CHUNK, S - row0);   // 964 or 960; both divisible by 4
    const int iters = rows >> 2;             // <= 241 -> u8 counters cannot overflow
    const float* base = x + (((size_t)b * S + row0 + soff) * F + f);

    constexpr int U = 8;                     // load-ahead for MLP
    int i = 0;
#pragma unroll 1
    for (; i + U <= iters; i += U) {
        float v[U];
#pragma unroll
        for (int u = 0; u < U; u++)
            v[u] = __ldcs(base + (size_t)(i + u) * (4 * F));
#pragma unroll
        for (int u = 0; u < U; u++) {
            // input in [0,1): (int)(v*128) is already in [0,127]; &127 is a free guard
            int bin = ((int)(v[u] * 128.0f)) & (BINS - 1);
            h8[bin] = (unsigned char)(h8[bin] + 1);      // private: no atomics
        }
    }
    for (; i < iters; i++) {
        float v = __ldcs(base + (size_t)i * (4 * F));
        int bin = ((int)(v * 128.0f)) & (BINS - 1);
        h8[bin] = (unsigned char)(h8[bin] + 1);
    }
    __syncthreads();

    // Intra-block reduction over the 4 s-offsets, dp4a byte extraction,
    // coalesced u32 dump. unit u -> (m = word = bins 4m..4m+3, fo = feature).
    // smem loads are conflict-free: bank = (t + m) & 31 with lane-distinct t.
    unsigned int* outp = g_scratch + ((size_t)c * B + b) * (BINS * F);
#pragma unroll
    for (int k = 0; k < 8; k++) {
        const int u = tid + THREADS * k;     // 0..2047
        const int fo = u & 63;
        const int m  = u >> 6;               // 0..31
        const int fh2 = fo >> 5, fl = fo & 31;
        unsigned int s0 = 0, s1 = 0, s2 = 0, s3 = 0;
#pragma unroll
        for (int s = 0; s < 4; s++) {
            const unsigned int v = sh[(unsigned)((2 * s + fh2) * 32 + fl) * HWORDS + m];
            s0 = __dp4a(v, 0x00000001u, s0);   // byte 0
            s1 = __dp4a(v, 0x00000100u, s1);   // byte 1
            s2 = __dp4a(v, 0x00010000u, s2);   // byte 2
            s3 = __dp4a(v, 0x01000000u, s3);   // byte 3
        }
        outp[(4 * m + 0) * F + fo] = s0;       // coalesced STG.32 per k,j
        outp[(4 * m + 1) * F + fo] = s1;
        outp[(4 * m + 2) * F + fo] = s2;
        outp[(4 * m + 3) * F + fo] = s3;
    }
}

__global__ void reduce_kernel(const float* __restrict__ wts, float* __restrict__ out) {
    const int idx = blockIdx.x * blockDim.x + threadIdx.x;  // 0..65535
    const int b = idx >> 11;                 // / 2048 float4-units per batch
    const int p4 = (idx & 2047) << 2;        // 16B-aligned position in [0, 8192)
    unsigned int a0 = 0, a1 = 0, a2 = 0, a3 = 0;
#pragma unroll
    for (int c = 0; c < NCHUNK; c++) {
        const uint4 v = *reinterpret_cast<const uint4*>(
            g_scratch + ((size_t)(c * B + b)) * (BINS * F) + p4);
        a0 += v.x; a1 += v.y; a2 += v.z; a3 += v.w;
    }
    const float4 wv = *reinterpret_cast<const float4*>(wts + p4);
    float4 o;
    o.x = (float)a0 * wv.x;
    o.y = (float)a1 * wv.y;
    o.z = (float)a2 * wv.z;
    o.w = (float)a3 * wv.w;
    *reinterpret_cast<float4*>(out + (size_t)b * (BINS * F) + p4) = o;
}

extern "C" void kernel_launch(void* const* d_in, const int* in_sizes, int n_in,
                              void* d_out, int out_size) {
    const float* x   = (const float*)d_in[0];
    const float* wts = (const float*)d_in[1];
    float* out = (float*)d_out;

    cudaFuncSetAttribute(hist_kernel, cudaFuncAttributeMaxDynamicSharedMemorySize, SMEM_BYTES);

    dim3 grid(NCHUNK, B);   // 17 x 32 = 544 blocks, single wave at occ 6
    dummy_kernel<<<1, 32>>>();
    hist_kernel<<<grid, THREADS, SMEM_BYTES>>>(x);
    reduce_kernel<<<(B * BINS * F / 4) / THREADS, THREADS>>>(wts, out);
    dummy_kernel<<<1, 32>>>();
}

// round 3
// speedup vs baseline: 1.4150x; 1.0150x over previous
#include <cuda_runtime.h>

// Histogram2d: x[32,16384,64] f32 in [0,1) -> hist[32,128,64] * weights[128,64]
//
// Per-thread private u8 histograms in SMEM (zero atomics), occ 6, single
// balanced wave (864 blocks), dp4a reduction, u16x2-packed partial dump,
// carry-free packed final reduce.

constexpr int B = 32, S = 16384, F = 64, BINS = 128;
constexpr int NCHUNK = 27;             // 26*608 + 576 = 16384; iters<=152 (u8-safe)
constexpr int CHUNK = 608;
constexpr int THREADS = 256;
constexpr int HWORDS = 33;             // 32 data words (128 u8 bins) + 1 pad (stride 33)
constexpr int SMEM_BYTES = THREADS * HWORDS * 4;   // 33792 B -> 6 blocks/SM

// Per-(chunk,batch) partial histograms, u16x2 packed (2 bins/word):
// [NCHUNK][B][BINS/2 * F] u32 = 14.2 MB
constexpr int PWORDS = (BINS / 2) * F;             // 4096 words per (chunk,batch)
__device__ __align__(16) unsigned int g_scratch[(size_t)NCHUNK * B * PWORDS];

__global__ __launch_bounds__(THREADS, 6)
void hist_kernel(const float* __restrict__ x) {
    extern __shared__ unsigned int sh[];
    const int tid = threadIdx.x;
    const int w = tid >> 5, l = tid & 31;

    // zero own (padded) histogram; private -> no sync needed before main loop
    unsigned int* my = sh + tid * HWORDS;
#pragma unroll
    for (int i = 0; i < HWORDS; i++) my[i] = 0u;
    unsigned char* h8 = reinterpret_cast<unsigned char*>(my);

    const int fh = w & 1;        // feature half: 0 -> f 0..31, 1 -> f 32..63
    const int soff = w >> 1;     // row offset mod 4
    const int f = fh * 32 + l;
    const int b = blockIdx.y, c = blockIdx.x;

    const int row0 = c * CHUNK;
    const int rows = min(CHUNK, S - row0);   // 608 or 576, both /4
    const int iters = rows >> 2;             // <=152 -> u8 cannot overflow
    const float* base = x + (((size_t)b * S + row0 + soff) * F + f);

    constexpr int U = 8;                     // load-ahead for MLP
    int i = 0;
#pragma unroll 1
    for (; i + U <= iters; i += U) {
        float v[U];
#pragma unroll
        for (int u = 0; u < U; u++)
            v[u] = __ldcs(base + (size_t)(i + u) * (4 * F));
#pragma unroll
        for (int u = 0; u < U; u++) {
            // input in [0,1): (int)(v*128) in [0,127]; &127 is a free guard
            int bin = ((int)(v[u] * 128.0f)) & (BINS - 1);
            h8[bin] = (unsigned char)(h8[bin] + 1);      // private: no atomics
        }
    }
    for (; i < iters; i++) {
        float v = __ldcs(base + (size_t)i * (4 * F));
        int bin = ((int)(v * 128.0f)) & (BINS - 1);
        h8[bin] = (unsigned char)(h8[bin] + 1);
    }
    __syncthreads();

    // Intra-block reduction over the 4 s-offsets (dp4a byte extraction),
    // u16x2-packed coalesced dump. Per-bin partial <= 4*152 = 608 < 2^16.
    // smem loads conflict-free: bank = (tsrc + m) & 31, lane-distinct tsrc.
    unsigned int* outp = g_scratch + ((size_t)c * B + b) * PWORDS;
#pragma unroll
    for (int k = 0; k < 8; k++) {
        const int u = tid + THREADS * k;     // 0..2047
        const int fo = u & 63;
        const int m  = u >> 6;               // word 0..31 -> bins 4m..4m+3
        const int fh2 = fo >> 5, fl = fo & 31;
        unsigned int s0 = 0, s1 = 0, s2 = 0, s3 = 0;
#pragma unroll
        for (int s = 0; s < 4; s++) {
            const unsigned int v = sh[(unsigned)((2 * s + fh2) * 32 + fl) * HWORDS + m];
            s0 = __dp4a(v, 0x00000001u, s0);
            s1 = __dp4a(v, 0x00000100u, s1);
            s2 = __dp4a(v, 0x00010000u, s2);
            s3 = __dp4a(v, 0x01000000u, s3);
        }
        outp[(2 * m + 0) * F + fo] = s0 | (s1 << 16);   // bins 4m, 4m+1
        outp[(2 * m + 1) * F + fo] = s2 | (s3 << 16);   // bins 4m+2, 4m+3
    }
}

__global__ void reduce_kernel(const float* __restrict__ wts, float* __restrict__ out) {
    // One thread per (batch, bin-pair, 4 features). 32*64*16 = 32768 threads.
    const int idx = blockIdx.x * blockDim.x + threadIdx.x;
    const int f4 = (idx & 15) << 2;          // feature group start
    const int p  = (idx >> 4) & 63;          // bin pair -> bins 2p, 2p+1
    const int b  = idx >> 10;
    // Packed u16x2 adds are carry-free: total per bin <= 16384 < 2^16.
    unsigned int a0 = 0, a1 = 0, a2 = 0, a3 = 0;
#pragma unroll
    for (int c = 0; c < NCHUNK; c++) {
        const uint4 v = *reinterpret_cast<const uint4*>(
            g_scratch + ((size_t)(c * B + b)) * PWORDS + p * F + f4);
        a0 += v.x; a1 += v.y; a2 += v.z; a3 += v.w;
    }
    const float4 wlo = *reinterpret_cast<const float4*>(wts + (2 * p) * F + f4);
    const float4 whi = *reinterpret_cast<const float4*>(wts + (2 * p + 1) * F + f4);
    float4 olo, ohi;
    olo.x = (float)(a0 & 0xFFFFu) * wlo.x;  ohi.x = (float)(a0 >> 16) * whi.x;
    olo.y = (float)(a1 & 0xFFFFu) * wlo.y;  ohi.y = (float)(a1 >> 16) * whi.y;
    olo.z = (float)(a2 & 0xFFFFu) * wlo.z;  ohi.z = (float)(a2 >> 16) * whi.z;
    olo.w = (float)(a3 & 0xFFFFu) * wlo.w;  ohi.w = (float)(a3 >> 16) * whi.w;
    float* ob = out + ((size_t)b * BINS + 2 * p) * F + f4;
    *reinterpret_cast<float4*>(ob)     = olo;
    *reinterpret_cast<float4*>(ob + F) = ohi;
}

extern "C" void kernel_launch(void* const* d_in, const int* in_sizes, int n_in,
                              void* d_out, int out_size) {
    const float* x   = (const float*)d_in[0];
    const float* wts = (const float*)d_in[1];
    float* out = (float*)d_out;

    cudaFuncSetAttribute(hist_kernel, cudaFuncAttributeMaxDynamicSharedMemorySize, SMEM_BYTES);

    dim3 grid(NCHUNK, B);   // 27 x 32 = 864 blocks, single wave at occ 6
    hist_kernel<<<grid, THREADS, SMEM_BYTES>>>(x);
    reduce_kernel<<<(B * (BINS / 2) * (F / 4)) / THREADS, THREADS>>>(wts, out);
}

// round 4
// speedup vs baseline: 1.8377x; 1.2987x over previous
#include <cuda_runtime.h>

// Histogram2d: x[32,16384,64] f32 in [0,1) -> hist[32,128,64] * weights[128,64]
//
// Per-thread private u8 histograms in SMEM with a BANK-ALIGNED layout:
// lane l's data always lives in bank l -> conflict degree 1 for every
// mainloop RMW, the zeroing, and the dump loads. Zero atomics anywhere.

constexpr int B = 32, S = 16384, F = 64, BINS = 128;
constexpr int NCHUNK = 27;             // 26*608 + 576 = 16384; iters<=152 (u8-safe)
constexpr int CHUNK = 608;
constexpr int THREADS = 256;
// smem: 8 warps x 1024 words. word(w, m, l) = w*1024 + m*32 + l  (bank = l)
constexpr int SMEM_BYTES = 8 * 1024 * 4;           // 32768 B -> 6 blocks/SM

// Per-(chunk,batch) partial histograms, u16x2 packed (2 bins/word):
constexpr int PWORDS = (BINS / 2) * F;             // 4096 words per (chunk,batch)
__device__ __align__(16) unsigned int g_scratch[(size_t)NCHUNK * B * PWORDS];

__global__ __launch_bounds__(THREADS, 6)
void hist_kernel(const float* __restrict__ x) {
    extern __shared__ unsigned int sh[];
    const int tid = threadIdx.x;
    const int w = tid >> 5, l = tid & 31;

    // zero own histogram: word (w, m, l) -> bank l, conflict-free
#pragma unroll
    for (int m = 0; m < 32; m++) sh[(w << 10) + (m << 5) + l] = 0u;

    unsigned char* sb = reinterpret_cast<unsigned char*>(sh);
    const unsigned int tbase = (w << 12) + (l << 2);   // byte base of this lane's hist

    const int fh = w & 1;        // feature half: 0 -> f 0..31, 1 -> f 32..63
    const int soff = w >> 1;     // row offset mod 4
    const int f = fh * 32 + l;
    const int b = blockIdx.y, c = blockIdx.x;

    const int row0 = c * CHUNK;
    const int rows = min(CHUNK, S - row0);   // 608 or 576
    const int iters = rows >> 2;             // 152 or 144 (both /8) -> u8 safe
    const float* base = x + (((size_t)b * S + row0 + soff) * F + f);

    constexpr int U = 8;                     // load-ahead for MLP
    int i = 0;
#pragma unroll 1
    for (; i + U <= iters; i += U) {
        float v[U];
#pragma unroll
        for (int u = 0; u < U; u++)
            v[u] = __ldcs(base + (size_t)(i + u) * (4 * F));
#pragma unroll
        for (int u = 0; u < U; u++) {
            // exact trunc(v*128): RZ-add truncates mantissa; bin bits = [16:23)
            const unsigned int bits = __float_as_uint(__fadd_rz(v[u], 1.0f));
            // byte offset: ((bin>>2)<<7) | (bin&3), bin = (bits>>16)&127
            const unsigned int off = (((bits >> 18) & 31u) << 7) | ((bits >> 16) & 3u);
            sb[tbase + off] = (unsigned char)(sb[tbase + off] + 1);  // bank l always
        }
    }
    for (; i < iters; i++) {
        const unsigned int bits = __float_as_uint(__fadd_rz(__ldcs(base + (size_t)i * (4 * F)), 1.0f));
        const unsigned int off = (((bits >> 18) & 31u) << 7) | ((bits >> 16) & 3u);
        sb[tbase + off] = (unsigned char)(sb[tbase + off] + 1);
    }
    __syncthreads();

    // Intra-block reduction over 4 s-offsets (dp4a byte extraction),
    // u16x2-packed coalesced dump. Loads hit bank fl = lane -> conflict-free.
    unsigned int* outp = g_scratch + ((size_t)c * B + b) * PWORDS;
#pragma unroll
    for (int k = 0; k < 8; k++) {
        const int u = tid + THREADS * k;     // 0..2047
        const int fo = u & 63;
        const int m  = u >> 6;               // word -> bins 4m..4m+3
        const int fh2 = fo >> 5, fl = fo & 31;
        unsigned int s0 = 0, s1 = 0, s2 = 0, s3 = 0;
#pragma unroll
        for (int s = 0; s < 4; s++) {
            const unsigned int v = sh[((2 * s + fh2) << 10) + (m << 5) + fl];
            s0 = __dp4a(v, 0x00000001u, s0);
            s1 = __dp4a(v, 0x00000100u, s1);
            s2 = __dp4a(v, 0x00010000u, s2);
            s3 = __dp4a(v, 0x01000000u, s3);
        }
        outp[(2 * m + 0) * F + fo] = s0 | (s1 << 16);   // bins 4m, 4m+1
        outp[(2 * m + 1) * F + fo] = s2 | (s3 << 16);   // bins 4m+2, 4m+3
    }
}

__global__ void reduce_kernel(const float* __restrict__ wts, float* __restrict__ out) {
    // 4-way chunk split per output group + smem combine (fixes occupancy).
    // idx: f4[0:4) cq[4:6) p[6:12) b[12:17)  -> 131072 threads
    const int idx = blockIdx.x * blockDim.x + threadIdx.x;
    const int tid = threadIdx.x;
    const int f4 = (idx & 15) << 2;
    const int cq = (idx >> 4) & 3;
    const int p  = (idx >> 6) & 63;
    const int b  = idx >> 12;

    const int c0 = cq * 7;
    const int c1 = min(c0 + 7, NCHUNK);      // 7,7,7,6 chunks
    unsigned int a0 = 0, a1 = 0, a2 = 0, a3 = 0;
#pragma unroll
    for (int c = c0; c < c1; c++) {
        const uint4 v = *reinterpret_cast<const uint4*>(
            g_scratch + ((size_t)(c * B + b)) * PWORDS + p * F + f4);
        a0 += v.x; a1 += v.y; a2 += v.z; a3 += v.w;   // packed u16x2, carry-free
    }
    __shared__ uint4 s4[THREADS];
    s4[tid] = make_uint4(a0, a1, a2, a3);
    __syncthreads();

    if (cq == 0) {
        const uint4 q1 = s4[tid + 16], q2 = s4[tid + 32], q3 = s4[tid + 48];
        a0 += q1.x + q2.x + q3.x;
        a1 += q1.y + q2.y + q3.y;
        a2 += q1.z + q2.z + q3.z;
        a3 += q1.w + q2.w + q3.w;
        const float4 wlo = *reinterpret_cast<const float4*>(wts + (2 * p) * F + f4);
        const float4 whi = *reinterpret_cast<const float4*>(wts + (2 * p + 1) * F + f4);
        float4 olo, ohi;
        olo.x = (float)(a0 & 0xFFFFu) * wlo.x;  ohi.x = (float)(a0 >> 16) * whi.x;
        olo.y = (float)(a1 & 0xFFFFu) * wlo.y;  ohi.y = (float)(a1 >> 16) * whi.y;
        olo.z = (float)(a2 & 0xFFFFu) * wlo.z;  ohi.z = (float)(a2 >> 16) * whi.z;
        olo.w = (float)(a3 & 0xFFFFu) * wlo.w;  ohi.w = (float)(a3 >> 16) * whi.w;
        float* ob = out + ((size_t)b * BINS + 2 * p) * F + f4;
        *reinterpret_cast<float4*>(ob)     = olo;
        *reinterpret_cast<float4*>(ob + F) = ohi;
    }
}

extern "C" void kernel_launch(void* const* d_in, const int* in_sizes, int n_in,
                              void* d_out, int out_size) {
    const float* x   = (const float*)d_in[0];
    const float* wts = (const float*)d_in[1];
    float* out = (float*)d_out;

    cudaFuncSetAttribute(hist_kernel, cudaFuncAttributeMaxDynamicSharedMemorySize, SMEM_BYTES);

    dim3 grid(NCHUNK, B);   // 27 x 32 = 864 blocks, single wave at occ 6
    hist_kernel<<<grid, THREADS, SMEM_BYTES>>>(x);
    reduce_kernel<<<(B * 64 * 4 * 16) / THREADS, THREADS>>>(wts, out);
}